// round 3
// baseline (speedup 1.0000x reference)
#include <cuda_runtime.h>
#include <cuda_bf16.h>
#include <math.h>

// ---------------------------------------------------------------------------
// GConvLSTM (ChebConv K=3, lambda_max=2) on GB300.
//
// Identity: Lhat(v) = -A v  (lambda_max == 2), so
//   cheb(v,W,b) = v@(W0-W2) + (Av)@(-W1) + (A^2 v)@(2*W2) + b
// Pipeline (no vector atomics — pull-style SpMM over per-call CSR):
//   0. detect:  edge_index dtype (int32 vs int64) -> g_is64 flag
//   1. init:    U[N][384] = [X | . | . | H | . | .]
//   2. zero:    deg/cnt/fill
//   3. deg:     deg[row] += w, cnt[row] += 1       (scalar atomics)
//   4. dinv:    rsqrt
//   5. scan:    rofs = exclusive_scan(cnt)         (single block)
//   6. scatter: CSR col + prenormalized weights
//   7. spmm1:   AX|AH   = A [X|H]     (warp/row gather, register acc)
//   8. spmm2:   A2X|A2H = A [AX|AH]
//   9. combine: fold 24 tensors into Wc[384][64][4] + bias
//  10. gemm_lstm: U @ Wc via packed fma.rn.f32x2, fused LSTM epilogue
// ---------------------------------------------------------------------------

#define N_  50000
#define E_  800000

typedef unsigned long long ull;

__device__ float g_U[(size_t)N_ * 384];   // [X|AX|A2X|H|AH|A2H] per row
__device__ float g_deg[N_];
__device__ float g_dinv[N_];
__device__ int   g_cnt[N_];
__device__ int   g_fill[N_];
__device__ int   g_rofs[N_ + 1];
__device__ int   g_col[E_];
__device__ float g_wv[E_];
__device__ float g_Wc[384 * 256];         // [k][j][g], g in {i,f,c,o}
__device__ float g_bias[256];             // [j][g]
__device__ int   g_is64;

// ---------------- helpers ----------------
__device__ __forceinline__ ull pack2(float x) {
    ull r;
    asm("mov.b64 %0, {%1, %1};" : "=l"(r) : "f"(x));
    return r;
}
__device__ __forceinline__ ull ffma2(ull a, ull b, ull c) {
    asm("fma.rn.f32x2 %0, %1, %2, %0;" : "+l"(c) : "l"(a), "l"(b));
    return c;
}
__device__ __forceinline__ void unpack2(ull v, float& lo, float& hi) {
    asm("mov.b64 {%0, %1}, %2;" : "=f"(lo), "=f"(hi) : "l"(v));
}
__device__ __forceinline__ float sigmoidf_(float z) {
    return 1.0f / (1.0f + expf(-z));
}
__device__ __forceinline__ int load_idx(const void* ei, long long pos, int is64) {
    if (is64) return (int)((const long long*)ei)[pos];
    return ((const int*)ei)[pos];
}

// ---------------- 0. dtype detection ----------------
// int64 indices < 2^31 have zero high words at odd int32 positions;
// int32 data there holds random row indices (never all-zero over 64 samples).
__global__ void k_detect(const int* __restrict__ ei) {
    if (threadIdx.x == 0) {
        int s = 0;
        for (int i = 0; i < 64; i++) s |= ei[2 * i + 1];
        g_is64 = (s == 0) ? 1 : 0;
    }
}

// ---------------- 1. init U (X and H sections only) ----------------
__global__ void k_init_u(const float* __restrict__ X, const float* __restrict__ H) {
    int idx = blockIdx.x * 256 + threadIdx.x;       // float4 units, N*32 total
    if (idx >= N_ * 32) return;
    int row = idx >> 5, c4 = idx & 31;
    float4 v;
    int dst;
    if (c4 < 16) { v = ((const float4*)X)[row * 16 + c4];        dst = row * 96 + c4; }
    else         { v = ((const float4*)H)[row * 16 + (c4 - 16)]; dst = row * 96 + 32 + c4; }
    ((float4*)g_U)[dst] = v;
}

// ---------------- 2. zero counters ----------------
__global__ void k_zero() {
    int i = blockIdx.x * 256 + threadIdx.x;
    if (i < N_) { g_deg[i] = 0.0f; g_cnt[i] = 0; g_fill[i] = 0; }
}

// ---------------- 3. degree + count ----------------
__global__ void k_deg(const void* __restrict__ ei, const float* __restrict__ ew) {
    int e = blockIdx.x * 256 + threadIdx.x;
    if (e >= E_) return;
    int is64 = g_is64;
    int r = load_idx(ei, e, is64);
    atomicAdd(&g_deg[r], ew[e]);
    atomicAdd(&g_cnt[r], 1);
}

// ---------------- 4. dinv ----------------
__global__ void k_dinv() {
    int i = blockIdx.x * 256 + threadIdx.x;
    if (i >= N_) return;
    float d = g_deg[i];
    g_dinv[i] = (d > 0.0f) ? rsqrtf(d) : 0.0f;
}

// ---------------- 5. exclusive scan of cnt -> rofs (single block) ----------------
__global__ __launch_bounds__(1024) void k_scan() {
    __shared__ int sh[1024];
    const int CH = (N_ + 1023) / 1024;  // 49
    int t = threadIdx.x;
    int base = t * CH;
    int s = 0;
    for (int i = 0; i < CH; i++) {
        int idx = base + i;
        if (idx < N_) s += g_cnt[idx];
    }
    sh[t] = s;
    __syncthreads();
    for (int off = 1; off < 1024; off <<= 1) {
        int v = (t >= off) ? sh[t - off] : 0;
        __syncthreads();
        sh[t] += v;
        __syncthreads();
    }
    int run = (t == 0) ? 0 : sh[t - 1];
    for (int i = 0; i < CH; i++) {
        int idx = base + i;
        if (idx < N_) { g_rofs[idx] = run; run += g_cnt[idx]; }
    }
    if (t == 0) g_rofs[N_] = E_;
}

// ---------------- 6. scatter edges into CSR ----------------
__global__ void k_scatter(const void* __restrict__ ei, const float* __restrict__ ew) {
    int e = blockIdx.x * 256 + threadIdx.x;
    if (e >= E_) return;
    int is64 = g_is64;
    int r = load_idx(ei, e, is64);
    int c = load_idx(ei, (long long)E_ + e, is64);
    int pos = g_rofs[r] + atomicAdd(&g_fill[r], 1);
    g_col[pos] = c;
    g_wv[pos] = g_dinv[r] * ew[e] * g_dinv[c];
}

// ---------------- 7/8. pull SpMM: one warp per destination row ----------------
// shift=0:  src = X(0..63)/H(192..255),   dst = AX(64..)/AH(256..)
// shift=64: src = AX/AH,                  dst = A2X/A2H
__global__ __launch_bounds__(256) void k_spmm_pull(int shift) {
    int row = (blockIdx.x * 256 + threadIdx.x) >> 5;
    if (row >= N_) return;
    int lane = threadIdx.x & 31;
    int off = (lane << 2) + ((lane >= 16) ? 128 : 0) + shift;

    int start = g_rofs[row];
    int end = g_rofs[row + 1];
    float ax = 0.f, ay = 0.f, az = 0.f, aw = 0.f;
    for (int j = start; j < end; ++j) {
        int c = g_col[j];       // broadcast across warp
        float w = g_wv[j];
        const float4 v = *(const float4*)&g_U[(size_t)c * 384 + off];
        ax += w * v.x; ay += w * v.y; az += w * v.z; aw += w * v.w;
    }
    *(float4*)&g_U[(size_t)row * 384 + off + 64] = make_float4(ax, ay, az, aw);
}

// ---------------- 9. combine weights ----------------
struct GPtrs {
    const float* Wx[4];  // Wxi, Wxf, Wxc, Wxo  each [3][64][64]
    const float* Wh[4];
    const float* bx[4];
    const float* bh[4];
    const float* bg[4];  // bi, bf, bc, bo each [64]
};

__global__ void k_combine(GPtrs p) {
    int idx = blockIdx.x * 256 + threadIdx.x;
    if (idx < 384 * 256) {
        int k = idx >> 8;
        int rem = idx & 255;
        int j = rem >> 2, g = rem & 3;
        int s = k / 64, kk = k % 64;
        const float* W = (s < 3) ? p.Wx[g] : p.Wh[g];
        int ss = s % 3;
        float val;
        if (ss == 0)      val = W[kk * 64 + j] - W[2 * 4096 + kk * 64 + j];
        else if (ss == 1) val = -W[4096 + kk * 64 + j];
        else              val = 2.0f * W[2 * 4096 + kk * 64 + j];
        g_Wc[k * 256 + j * 4 + g] = val;
    } else if (idx < 384 * 256 + 256) {
        int r = idx - 384 * 256;
        int j = r >> 2, g = r & 3;
        g_bias[j * 4 + g] = p.bx[g][j] + p.bh[g][j] + p.bg[g][j];
    }
}

// ---------------- 10. GEMM + LSTM epilogue ----------------
// out[50000][256] = U[50000][384] @ Wc[384][256] (+bias), then gate math.
// Block: 32 rows, 256 threads. warp = 4-row group, lane = column pair
// (cols j0=2*lane, j1=2*lane+1, each with 4 gates interleaved).
__global__ __launch_bounds__(256) void k_gemm_lstm(const float* __restrict__ Cin,
                                                   float* __restrict__ out) {
    __shared__ float Us[32 * 32];
    __shared__ float Ws[32 * 256];
    int t = threadIdx.x, lane = t & 31, warp = t >> 5;
    int m0 = blockIdx.x * 32;

    ull acc[4][4];
#pragma unroll
    for (int r = 0; r < 4; r++)
#pragma unroll
        for (int p = 0; p < 4; p++) acc[r][p] = 0ULL;

    const float4* Wc4 = (const float4*)g_Wc;

    for (int kc = 0; kc < 12; ++kc) {
        // load U tile 32x32
        {
            int r = t >> 3, koff = (t & 7) << 2;
            int row = m0 + r;
            float4 v = make_float4(0.f, 0.f, 0.f, 0.f);
            if (row < N_) v = *(const float4*)&g_U[(size_t)row * 384 + kc * 32 + koff];
            *(float4*)&Us[r * 32 + koff] = v;
        }
        // load W tile 32x256
        {
            float4* Ws4 = (float4*)Ws;
            int base = kc * 2048;
#pragma unroll
            for (int i = 0; i < 8; i++) Ws4[t + (i << 8)] = Wc4[base + t + (i << 8)];
        }
        __syncthreads();

#pragma unroll
        for (int k = 0; k < 32; k++) {
            ull A[4];
#pragma unroll
            for (int r = 0; r < 4; r++) A[r] = pack2(Us[(warp * 4 + r) * 32 + k]);
            const ulonglong2* wp = (const ulonglong2*)&Ws[k * 256 + lane * 8];
            ulonglong2 w01 = wp[0];
            ulonglong2 w23 = wp[1];
#pragma unroll
            for (int r = 0; r < 4; r++) {
                acc[r][0] = ffma2(A[r], w01.x, acc[r][0]);
                acc[r][1] = ffma2(A[r], w01.y, acc[r][1]);
                acc[r][2] = ffma2(A[r], w23.x, acc[r][2]);
                acc[r][3] = ffma2(A[r], w23.y, acc[r][3]);
            }
        }
        __syncthreads();
    }

    // epilogue: bias + gate activations + LSTM update
    float4 bb0 = ((const float4*)g_bias)[lane * 2];       // j0: (bi, bf, bc, bo)
    float4 bb1 = ((const float4*)g_bias)[lane * 2 + 1];   // j1

#pragma unroll
    for (int r = 0; r < 4; r++) {
        int row = m0 + warp * 4 + r;
        if (row >= N_) continue;
        float2 cold = *(const float2*)&Cin[(size_t)row * 64 + lane * 2];
        float h2[2], c2[2];
#pragma unroll
        for (int jj = 0; jj < 2; jj++) {
            float zi, zf, zc, zo;
            unpack2(acc[r][jj * 2], zi, zf);
            unpack2(acc[r][jj * 2 + 1], zc, zo);
            float4 bb = jj ? bb1 : bb0;
            zi += bb.x; zf += bb.y; zc += bb.z; zo += bb.w;
            float I = sigmoidf_(zi);
            float F = sigmoidf_(zf);
            float T = tanhf(zc);
            float O = sigmoidf_(zo);
            float co = jj ? cold.y : cold.x;
            float cn = F * co + I * T;
            c2[jj] = cn;
            h2[jj] = O * tanhf(cn);
        }
        *(float2*)&out[(size_t)row * 64 + lane * 2] = make_float2(h2[0], h2[1]);
        *(float2*)&out[(size_t)N_ * 64 + (size_t)row * 64 + lane * 2] =
            make_float2(c2[0], c2[1]);
    }
}

// ---------------- launch ----------------
extern "C" void kernel_launch(void* const* d_in, const int* in_sizes, int n_in,
                              void* d_out, int out_size) {
    const float* X  = (const float*)d_in[0];
    const void*  EI = d_in[1];
    const float* EW = (const float*)d_in[2];
    const float* H  = (const float*)d_in[3];
    const float* C  = (const float*)d_in[4];

    GPtrs p;
    // d_in order: 5 Wxi, 6 bxi, 7 Whi, 8 bhi, 9 Wxf, 10 bxf, 11 Whf, 12 bhf,
    //            13 Wxc, 14 bxc, 15 Whc, 16 bhc, 17 Wxo, 18 bxo, 19 Who, 20 bho,
    //            21 bi, 22 bf, 23 bc, 24 bo
    for (int g = 0; g < 4; g++) {
        p.Wx[g] = (const float*)d_in[5 + 4 * g];
        p.bx[g] = (const float*)d_in[6 + 4 * g];
        p.Wh[g] = (const float*)d_in[7 + 4 * g];
        p.bh[g] = (const float*)d_in[8 + 4 * g];
        p.bg[g] = (const float*)d_in[21 + g];
    }
    float* out = (float*)d_out;

    k_detect<<<1, 32>>>((const int*)EI);
    k_init_u<<<(N_ * 32 + 255) / 256, 256>>>(X, H);
    k_zero<<<(N_ + 255) / 256, 256>>>();
    k_deg<<<(E_ + 255) / 256, 256>>>(EI, EW);
    k_dinv<<<(N_ + 255) / 256, 256>>>();
    k_scan<<<1, 1024>>>();
    k_scatter<<<(E_ + 255) / 256, 256>>>(EI, EW);
    k_spmm_pull<<<(N_ * 32 + 255) / 256, 256>>>(0);
    k_spmm_pull<<<(N_ * 32 + 255) / 256, 256>>>(64);
    k_combine<<<(384 * 256 + 256 + 255) / 256, 256>>>(p);
    k_gemm_lstm<<<(N_ + 31) / 32, 256>>>(C, out);
}

// round 4
// speedup vs baseline: 1.2633x; 1.2633x over previous
#include <cuda_runtime.h>
#include <cuda_bf16.h>
#include <math.h>

// ---------------------------------------------------------------------------
// GConvLSTM (ChebConv K=3, lambda_max=2) on GB300.
//
// Identity: Lhat(v) = -A v  (lambda_max == 2), so
//   cheb(v,W,b) = v@(W0-W2) + (Av)@(-W1) + (A^2 v)@(2*W2) + b
// Pipeline:
//   0. detect edge_index dtype (int32 vs int64)
//   1. init U[N][384] = [X | . | . | H | . | .]
//   2-6. build CSR (counts, scan, scatter packed {col,w})
//   7/8. pull-SpMM x2 (warp/row, 4-way edge unroll)
//   9. combine weights into SoA-packed Wc[384][4][32]x2 + bias
//  10. gemm_lstm: 64-row blocks, 8 rows/thread, conflict-free LDS.64 W
//      fetch, packed fma.rn.f32x2, fused LSTM epilogue
// ---------------------------------------------------------------------------

#define N_  50000
#define E_  800000

typedef unsigned long long ull;

__device__ float g_U[(size_t)N_ * 384];   // [X|AX|A2X|H|AH|A2H] per row
__device__ float g_deg[N_];
__device__ float g_dinv[N_];
__device__ int   g_cnt[N_];
__device__ int   g_fill[N_];
__device__ int   g_rofs[N_ + 1];
__device__ int2  g_cw[E_];                // packed {col, bits(w)}
__device__ float g_Wc[384 * 256];         // [k][q][lane] float2 SoA (see combine)
__device__ float g_bias[256];             // [j][g]
__device__ int   g_is64;

// ---------------- helpers ----------------
__device__ __forceinline__ ull pack2(float x) {
    ull r;
    asm("mov.b64 %0, {%1, %1};" : "=l"(r) : "f"(x));
    return r;
}
__device__ __forceinline__ ull ffma2(ull a, ull b, ull c) {
    asm("fma.rn.f32x2 %0, %1, %2, %0;" : "+l"(c) : "l"(a), "l"(b));
    return c;
}
__device__ __forceinline__ void unpack2(ull v, float& lo, float& hi) {
    asm("mov.b64 {%0, %1}, %2;" : "=f"(lo), "=f"(hi) : "l"(v));
}
__device__ __forceinline__ float sigmoidf_(float z) {
    return 1.0f / (1.0f + expf(-z));
}
__device__ __forceinline__ int load_idx(const void* ei, long long pos, int is64) {
    if (is64) return (int)((const long long*)ei)[pos];
    return ((const int*)ei)[pos];
}

// ---------------- 0. dtype detection ----------------
__global__ void k_detect(const int* __restrict__ ei) {
    if (threadIdx.x == 0) {
        int s = 0;
        for (int i = 0; i < 64; i++) s |= ei[2 * i + 1];
        g_is64 = (s == 0) ? 1 : 0;
    }
}

// ---------------- 1. init U (X and H sections) ----------------
__global__ void k_init_u(const float* __restrict__ X, const float* __restrict__ H) {
    int idx = blockIdx.x * 256 + threadIdx.x;       // float4 units, N*32 total
    if (idx >= N_ * 32) return;
    int row = idx >> 5, c4 = idx & 31;
    float4 v;
    int dst;
    if (c4 < 16) { v = ((const float4*)X)[row * 16 + c4];        dst = row * 96 + c4; }
    else         { v = ((const float4*)H)[row * 16 + (c4 - 16)]; dst = row * 96 + 32 + c4; }
    ((float4*)g_U)[dst] = v;
}

// ---------------- 2. zero counters ----------------
__global__ void k_zero() {
    int i = blockIdx.x * 256 + threadIdx.x;
    if (i < N_) { g_deg[i] = 0.0f; g_cnt[i] = 0; g_fill[i] = 0; }
}

// ---------------- 3. degree + count ----------------
__global__ void k_deg(const void* __restrict__ ei, const float* __restrict__ ew) {
    int e = blockIdx.x * 256 + threadIdx.x;
    if (e >= E_) return;
    int is64 = g_is64;
    int r = load_idx(ei, e, is64);
    atomicAdd(&g_deg[r], ew[e]);
    atomicAdd(&g_cnt[r], 1);
}

// ---------------- 4. dinv ----------------
__global__ void k_dinv() {
    int i = blockIdx.x * 256 + threadIdx.x;
    if (i >= N_) return;
    float d = g_deg[i];
    g_dinv[i] = (d > 0.0f) ? rsqrtf(d) : 0.0f;
}

// ---------------- 5. exclusive scan of cnt -> rofs (single block) ----------------
__global__ __launch_bounds__(1024) void k_scan() {
    __shared__ int sh[1024];
    const int CH = (N_ + 1023) / 1024;  // 49
    int t = threadIdx.x;
    int base = t * CH;
    int s = 0;
    for (int i = 0; i < CH; i++) {
        int idx = base + i;
        if (idx < N_) s += g_cnt[idx];
    }
    sh[t] = s;
    __syncthreads();
    for (int off = 1; off < 1024; off <<= 1) {
        int v = (t >= off) ? sh[t - off] : 0;
        __syncthreads();
        sh[t] += v;
        __syncthreads();
    }
    int run = (t == 0) ? 0 : sh[t - 1];
    for (int i = 0; i < CH; i++) {
        int idx = base + i;
        if (idx < N_) { g_rofs[idx] = run; run += g_cnt[idx]; }
    }
    if (t == 0) g_rofs[N_] = E_;
}

// ---------------- 6. scatter edges into CSR (packed int2) ----------------
__global__ void k_scatter(const void* __restrict__ ei, const float* __restrict__ ew) {
    int e = blockIdx.x * 256 + threadIdx.x;
    if (e >= E_) return;
    int is64 = g_is64;
    int r = load_idx(ei, e, is64);
    int c = load_idx(ei, (long long)E_ + e, is64);
    int pos = g_rofs[r] + atomicAdd(&g_fill[r], 1);
    float nw = g_dinv[r] * ew[e] * g_dinv[c];
    g_cw[pos] = make_int2(c, __float_as_int(nw));
}

// ---------------- 7/8. pull SpMM: one warp per row, 4-way edge unroll ----------
// shift=0:  src = X(0..63)/H(192..255),   dst = AX(64..)/AH(256..)
// shift=64: src = AX/AH,                  dst = A2X/A2H
__global__ __launch_bounds__(256) void k_spmm_pull(int shift) {
    int row = (blockIdx.x * 256 + threadIdx.x) >> 5;
    if (row >= N_) return;
    int lane = threadIdx.x & 31;
    int off = (lane << 2) + ((lane >= 16) ? 128 : 0) + shift;

    int start = g_rofs[row];
    int end = g_rofs[row + 1];

    float4 a0 = make_float4(0.f, 0.f, 0.f, 0.f);
    float4 a1 = a0, a2 = a0, a3 = a0;

    int j = start;
    for (; j + 4 <= end; j += 4) {
        int2 cw0 = g_cw[j];
        int2 cw1 = g_cw[j + 1];
        int2 cw2 = g_cw[j + 2];
        int2 cw3 = g_cw[j + 3];
        const float4 v0 = *(const float4*)&g_U[(size_t)cw0.x * 384 + off];
        const float4 v1 = *(const float4*)&g_U[(size_t)cw1.x * 384 + off];
        const float4 v2 = *(const float4*)&g_U[(size_t)cw2.x * 384 + off];
        const float4 v3 = *(const float4*)&g_U[(size_t)cw3.x * 384 + off];
        float w0 = __int_as_float(cw0.y), w1 = __int_as_float(cw1.y);
        float w2 = __int_as_float(cw2.y), w3 = __int_as_float(cw3.y);
        a0.x += w0 * v0.x; a0.y += w0 * v0.y; a0.z += w0 * v0.z; a0.w += w0 * v0.w;
        a1.x += w1 * v1.x; a1.y += w1 * v1.y; a1.z += w1 * v1.z; a1.w += w1 * v1.w;
        a2.x += w2 * v2.x; a2.y += w2 * v2.y; a2.z += w2 * v2.z; a2.w += w2 * v2.w;
        a3.x += w3 * v3.x; a3.y += w3 * v3.y; a3.z += w3 * v3.z; a3.w += w3 * v3.w;
    }
    for (; j < end; ++j) {
        int2 cw = g_cw[j];
        float w = __int_as_float(cw.y);
        const float4 v = *(const float4*)&g_U[(size_t)cw.x * 384 + off];
        a0.x += w * v.x; a0.y += w * v.y; a0.z += w * v.z; a0.w += w * v.w;
    }
    a0.x += a1.x + a2.x + a3.x;
    a0.y += a1.y + a2.y + a3.y;
    a0.z += a1.z + a2.z + a3.z;
    a0.w += a1.w + a2.w + a3.w;
    *(float4*)&g_U[(size_t)row * 384 + off + 64] = a0;
}

// ---------------- 9. combine weights (SoA-packed for conflict-free LDS) ------
// Element (k, j, g)  ->  float2 slot (k*4 + (j&1)*2 + g/2)*32 + (j>>1),
//                        component g&1.
// Thread `lane` in the GEMM owns columns j0=2*lane, j1=2*lane+1; its 4
// float2 fetches per k are at [k*4+q]*32 + lane  -> lane-stride 8 B,
// conflict-free LDS.64.
struct GPtrs {
    const float* Wx[4];  // Wxi, Wxf, Wxc, Wxo  each [3][64][64]
    const float* Wh[4];
    const float* bx[4];
    const float* bh[4];
    const float* bg[4];  // bi, bf, bc, bo each [64]
};

__global__ void k_combine(GPtrs p) {
    int idx = blockIdx.x * 256 + threadIdx.x;
    if (idx < 384 * 256) {
        int k = idx >> 8;
        int rem = idx & 255;
        int j = rem >> 2, g = rem & 3;
        int s = k / 64, kk = k % 64;
        const float* W = (s < 3) ? p.Wx[g] : p.Wh[g];
        int ss = s % 3;
        float val;
        if (ss == 0)      val = W[kk * 64 + j] - W[2 * 4096 + kk * 64 + j];
        else if (ss == 1) val = -W[4096 + kk * 64 + j];
        else              val = 2.0f * W[2 * 4096 + kk * 64 + j];
        int f2 = (k * 4 + (j & 1) * 2 + (g >> 1)) * 32 + (j >> 1);
        g_Wc[f2 * 2 + (g & 1)] = val;
    } else if (idx < 384 * 256 + 256) {
        int r = idx - 384 * 256;
        int j = r >> 2, g = r & 3;
        g_bias[j * 4 + g] = p.bx[g][j] + p.bh[g][j] + p.bg[g][j];
    }
}

// ---------------- 10. GEMM + LSTM epilogue ----------------
// out = U[50000][384] @ Wc[384][256] (+bias), then gate math.
// Block: 64 rows, 256 threads (8 warps). warp = 8-row group, lane = column
// pair (j0=2*lane, j1=2*lane+1, 4 gates each).
__global__ __launch_bounds__(256) void k_gemm_lstm(const float* __restrict__ Cin,
                                                   float* __restrict__ out) {
    __shared__ float Us[64 * 32];
    __shared__ float Ws[32 * 256];     // [k][q][lane] float2 SoA
    int t = threadIdx.x, lane = t & 31, warp = t >> 5;
    int m0 = blockIdx.x * 64;

    ull acc[8][4];
#pragma unroll
    for (int r = 0; r < 8; r++)
#pragma unroll
        for (int q = 0; q < 4; q++) acc[r][q] = 0ULL;

    const float4* Wc4 = (const float4*)g_Wc;

    for (int kc = 0; kc < 12; ++kc) {
        // load U tile 64x32 (512 float4, 2 per thread)
        {
#pragma unroll
            for (int i = 0; i < 2; i++) {
                int v = t + i * 256;
                int r = v >> 3, koff = (v & 7) << 2;
                int row = m0 + r;
                float4 val = make_float4(0.f, 0.f, 0.f, 0.f);
                if (row < N_) val = *(const float4*)&g_U[(size_t)row * 384 + kc * 32 + koff];
                *(float4*)&Us[r * 32 + koff] = val;
            }
        }
        // load W tile 32x256 (same layout in global)
        {
            float4* Ws4 = (float4*)Ws;
            int base = kc * 2048;
#pragma unroll
            for (int i = 0; i < 8; i++) Ws4[t + (i << 8)] = Wc4[base + t + (i << 8)];
        }
        __syncthreads();

        const ull* Wsq = (const ull*)Ws;
#pragma unroll 8
        for (int k = 0; k < 32; k++) {
            ull w0 = Wsq[(k * 4 + 0) * 32 + lane];
            ull w1 = Wsq[(k * 4 + 1) * 32 + lane];
            ull w2 = Wsq[(k * 4 + 2) * 32 + lane];
            ull w3 = Wsq[(k * 4 + 3) * 32 + lane];
#pragma unroll
            for (int r = 0; r < 8; r++) {
                ull A = pack2(Us[(warp * 8 + r) * 32 + k]);
                acc[r][0] = ffma2(A, w0, acc[r][0]);
                acc[r][1] = ffma2(A, w1, acc[r][1]);
                acc[r][2] = ffma2(A, w2, acc[r][2]);
                acc[r][3] = ffma2(A, w3, acc[r][3]);
            }
        }
        __syncthreads();
    }

    // epilogue: bias + gate activations + LSTM update
    float4 bb0 = ((const float4*)g_bias)[lane * 2];       // j0: (bi, bf, bc, bo)
    float4 bb1 = ((const float4*)g_bias)[lane * 2 + 1];   // j1

#pragma unroll
    for (int r = 0; r < 8; r++) {
        int row = m0 + warp * 8 + r;
        if (row >= N_) continue;
        float2 cold = *(const float2*)&Cin[(size_t)row * 64 + lane * 2];
        float h2[2], c2[2];
#pragma unroll
        for (int jj = 0; jj < 2; jj++) {
            float zi, zf, zc, zo;
            unpack2(acc[r][jj * 2], zi, zf);
            unpack2(acc[r][jj * 2 + 1], zc, zo);
            float4 bb = jj ? bb1 : bb0;
            zi += bb.x; zf += bb.y; zc += bb.z; zo += bb.w;
            float I = sigmoidf_(zi);
            float F = sigmoidf_(zf);
            float T = tanhf(zc);
            float O = sigmoidf_(zo);
            float co = jj ? cold.y : cold.x;
            float cn = F * co + I * T;
            c2[jj] = cn;
            h2[jj] = O * tanhf(cn);
        }
        *(float2*)&out[(size_t)row * 64 + lane * 2] = make_float2(h2[0], h2[1]);
        *(float2*)&out[(size_t)N_ * 64 + (size_t)row * 64 + lane * 2] =
            make_float2(c2[0], c2[1]);
    }
}

// ---------------- launch ----------------
extern "C" void kernel_launch(void* const* d_in, const int* in_sizes, int n_in,
                              void* d_out, int out_size) {
    const float* X  = (const float*)d_in[0];
    const void*  EI = d_in[1];
    const float* EW = (const float*)d_in[2];
    const float* H  = (const float*)d_in[3];
    const float* C  = (const float*)d_in[4];

    GPtrs p;
    for (int g = 0; g < 4; g++) {
        p.Wx[g] = (const float*)d_in[5 + 4 * g];
        p.bx[g] = (const float*)d_in[6 + 4 * g];
        p.Wh[g] = (const float*)d_in[7 + 4 * g];
        p.bh[g] = (const float*)d_in[8 + 4 * g];
        p.bg[g] = (const float*)d_in[21 + g];
    }
    float* out = (float*)d_out;

    k_detect<<<1, 32>>>((const int*)EI);
    k_init_u<<<(N_ * 32 + 255) / 256, 256>>>(X, H);
    k_zero<<<(N_ + 255) / 256, 256>>>();
    k_deg<<<(E_ + 255) / 256, 256>>>(EI, EW);
    k_dinv<<<(N_ + 255) / 256, 256>>>();
    k_scan<<<1, 1024>>>();
    k_scatter<<<(E_ + 255) / 256, 256>>>(EI, EW);
    k_spmm_pull<<<(N_ * 32 + 255) / 256, 256>>>(0);
    k_spmm_pull<<<(N_ * 32 + 255) / 256, 256>>>(64);
    k_combine<<<(384 * 256 + 256 + 255) / 256, 256>>>(p);
    k_gemm_lstm<<<(N_ + 63) / 64, 256>>>(C, out);
}